// round 15
// baseline (speedup 1.0000x reference)
#include <cuda_runtime.h>
#include <cuda_fp16.h>
#include <cstdint>

// Problem constants (fixed shapes per reference)
#define P_POINTS   1500000
#define TOTAL_BEV  40000
#define N_FEAT     4224        // feature rows
#define NCH        80
#define NCH4       20          // 80 channels as 20 x (4 ch)
#define BATCH      32          // points staged per warp iteration
#define WPB        2           // warps per block (64 threads): max-of-2 block
                               // retirement vs max-of-8 -> ~10% less dead-warp
                               // residency with Poisson(37.5) bin lengths
#define TPB        (WPB * 32)

#define CONV_THREADS  (N_FEAT * NCH4)          // 84480: one float4 -> uint2 each
#define CONV_BLOCKS   ((CONV_THREADS + 255) / 256)        // 330
#define SEG_BLOCKS    ((TOTAL_BEV + 1 + 255) / 256)       // 157

// Scratch (no cudaMalloc allowed)
__device__ int   g_seg[TOTAL_BEV + 1];        // seg[b] = lower_bound(ranks_bev, b)
__device__ uint2 g_feat_h[N_FEAT * NCH4];     // feat fp16: row = 20 x uint2 (4 halfs), 160 B/row

// ---------------------------------------------------------------------------
// Dtype detection: index values are < 2^31, so if the buffer is really int64
// the high 32 bits of the first 4 u64 words are all zero.
// ---------------------------------------------------------------------------
__device__ __forceinline__ int detect64(const void* __restrict__ rd) {
    const unsigned long long* u = (const unsigned long long*)rd;
    unsigned long long h = (__ldg(u + 0) >> 32) | (__ldg(u + 1) >> 32) |
                           (__ldg(u + 2) >> 32) | (__ldg(u + 3) >> 32);
    return h == 0ULL;
}

__device__ __forceinline__ int ld_idx32(const void* __restrict__ p, int i, int is64) {
    if (is64) return (int)__ldg((const long long*)p + i);
    return __ldg((const int*)p + i);
}

// Packed f32x2 helpers (Blackwell f32x2 pipe; identical IEEE fma per lane)
__device__ __forceinline__ void fma_f32x2(unsigned long long& acc,
                                          unsigned long long a,
                                          unsigned long long b) {
    asm("fma.rn.f32x2 %0, %1, %2, %0;" : "+l"(acc) : "l"(a), "l"(b));
}
__device__ __forceinline__ unsigned long long pack_f32x2(float lo, float hi) {
    unsigned long long r;
    asm("mov.b64 %0, {%1, %2};" : "=l"(r) : "f"(lo), "f"(hi));
    return r;
}
__device__ __forceinline__ float2 unpack_f32x2(unsigned long long v) {
    float2 r;
    asm("mov.b64 {%0, %1}, %2;" : "=f"(r.x), "=f"(r.y) : "l"(v));
    return r;
}

// ---------------------------------------------------------------------------
// Kernel 1 (fused prep):
//   blocks [0, CONV_BLOCKS)           : feat fp32 -> fp16 (float4 -> uint2)
//   blocks [CONV_BLOCKS, +SEG_BLOCKS) : per-bin lower_bound over ranks_bev
// (pre-pack experiment from R14 reverted: its 36 MB DRAM round-trip cost
//  +5.1 us of prep for only -3.1 us of main-kernel time)
// ---------------------------------------------------------------------------
__global__ void prep_kernel(const float* __restrict__ feat,
                            const void* __restrict__ ranks_bev,
                            const void* __restrict__ ranks_depth) {
    if (blockIdx.x < CONV_BLOCKS) {
        int i = blockIdx.x * blockDim.x + threadIdx.x;   // over N_FEAT*NCH4 float4s
        if (i < CONV_THREADS) {
            float4 v = __ldg((const float4*)feat + i);
            uint2 q;
            *(__half2*)&q.x = __float22half2_rn(make_float2(v.x, v.y));
            *(__half2*)&q.y = __float22half2_rn(make_float2(v.z, v.w));
            g_feat_h[i] = q;
        }
        return;
    }

    int b = (blockIdx.x - CONV_BLOCKS) * blockDim.x + threadIdx.x;
    if (b > TOTAL_BEV) return;
    const int is64 = detect64(ranks_depth);

    // ranks_bev is sorted-uniform: lower_bound(b) ~ b*P/B, sd <~ 620. Bracket
    // the interpolation guess (w=2048 > 3 sigma), widen on rare miss, then an
    // 11-step binary search.
    long long guess = (long long)b * P_POINTS / TOTAL_BEV;
    int lo = 0, hi = P_POINTS;
    int w = 2048;
    while (w < P_POINTS) {
        int l = (int)guess - w; if (l < 0) l = 0;
        int h = (int)guess + w; if (h > P_POINTS) h = P_POINTS;
        bool okL = (l == 0)        || (ld_idx32(ranks_bev, l - 1, is64) < b);
        bool okR = (h == P_POINTS) || (ld_idx32(ranks_bev, h,     is64) >= b);
        if (okL && okR) { lo = l; hi = h; break; }
        w <<= 2;
    }
    while (lo < hi) {
        int m = (lo + hi) >> 1;
        if (ld_idx32(ranks_bev, m, is64) < b) lo = m + 1; else hi = m;
    }
    g_seg[b] = lo;
}

// ---------------------------------------------------------------------------
// Kernel 2: one warp per BEV bin, smem-packed staging, fp16 feat.
// Stage + consume are byte-identical to R13 (FROZEN: dependent gather chain
// in stage, constant-trip-count fast path, LDS.128 point-pairing, f32x2 FMA,
// padded tail). Only the launch geometry changed: 64-thread blocks.
// ---------------------------------------------------------------------------
__global__ void __launch_bounds__(TPB) bev_pool_kernel(
    const float* __restrict__ depth,       // [498432]
    const void* __restrict__ ranks_depth,  // [P]
    const void* __restrict__ ranks_feat,   // [P]
    float* __restrict__ out)               // [40000, 80]
{
    __shared__ __align__(16) unsigned long long stage[WPB][BATCH];

    const int warp = (blockIdx.x * blockDim.x + threadIdx.x) >> 5;
    const int wib  = (threadIdx.x >> 5);   // warp in block
    const int lane = threadIdx.x & 31;
    if (warp >= TOTAL_BEV) return;

    const int is64 = detect64(ranks_depth);
    const int lo = g_seg[warp];
    const int hi = g_seg[warp + 1];

    const int  active = (lane < NCH4);
    const int  c4     = active ? lane : 0;   // idle lanes shadow lane 0's line
    const uint2* __restrict__ fvc = g_feat_h + c4;
    const uint4* __restrict__ stg4 = (const uint4*)&stage[wib][0];

    unsigned long long a01 = 0ULL, a23 = 0ULL;   // f32x2 accumulators

    for (int p = lo; p < hi; p += BATCH) {
        const int n = min(BATCH, hi - p);

        // ---- stage: coalesced idx loads + depth gather, pack to smem ----
        // pack = (d_bits << 32) | (rf * NCH4): consume needs no multiply
        unsigned long long packed = 0ULL;
        if (lane < n) {
            int   rd = ld_idx32(ranks_depth, p + lane, is64);
            int   rf = ld_idx32(ranks_feat,  p + lane, is64);
            float d  = __ldg(depth + rd);
            packed = ((unsigned long long)__float_as_uint(d) << 32)
                   | (unsigned)(rf * NCH4);
        }
        stage[wib][lane] = packed;
        __syncwarp();

        // ---- consume: 2 points per LDS.128, f32x2 FMA ----
        if (n == BATCH) {
            // constant trip count: ptxas fully pipelines this (do not touch)
#pragma unroll 4
            for (int j = 0; j < BATCH / 2; ++j) {
                uint4 u = stg4[j];                 // pts 2j (x,y) and 2j+1 (z,w)
                uint2 q0 = __ldg(fvc + u.x);
                uint2 q1 = __ldg(fvc + u.z);
                unsigned long long d0 = pack_f32x2(__uint_as_float(u.y), __uint_as_float(u.y));
                unsigned long long d1 = pack_f32x2(__uint_as_float(u.w), __uint_as_float(u.w));
                float2 p00 = __half22float2(*(const __half2*)&q0.x);
                float2 p01 = __half22float2(*(const __half2*)&q0.y);
                float2 p10 = __half22float2(*(const __half2*)&q1.x);
                float2 p11 = __half22float2(*(const __half2*)&q1.y);
                fma_f32x2(a01, pack_f32x2(p00.x, p00.y), d0);
                fma_f32x2(a23, pack_f32x2(p01.x, p01.y), d0);
                fma_f32x2(a01, pack_f32x2(p10.x, p10.y), d1);
                fma_f32x2(a23, pack_f32x2(p11.x, p11.y), d1);
            }
        } else {
            // tail: pad to multiple of 8 points (= 4 pairs); padded slots are
            // (d=0, off=0) -> contribute exactly 0 (row 0 stays L1-hot)
            const int m4 = ((n + 7) & ~7) >> 1;
#pragma unroll 4
            for (int j = 0; j < m4; ++j) {
                uint4 u = stg4[j];
                uint2 q0 = __ldg(fvc + u.x);
                uint2 q1 = __ldg(fvc + u.z);
                unsigned long long d0 = pack_f32x2(__uint_as_float(u.y), __uint_as_float(u.y));
                unsigned long long d1 = pack_f32x2(__uint_as_float(u.w), __uint_as_float(u.w));
                float2 p00 = __half22float2(*(const __half2*)&q0.x);
                float2 p01 = __half22float2(*(const __half2*)&q0.y);
                float2 p10 = __half22float2(*(const __half2*)&q1.x);
                float2 p11 = __half22float2(*(const __half2*)&q1.y);
                fma_f32x2(a01, pack_f32x2(p00.x, p00.y), d0);
                fma_f32x2(a23, pack_f32x2(p01.x, p01.y), d0);
                fma_f32x2(a01, pack_f32x2(p10.x, p10.y), d1);
                fma_f32x2(a23, pack_f32x2(p11.x, p11.y), d1);
            }
        }
        __syncwarp();   // protect stage[] before next overwrite
    }

    if (active) {
        float2 r01 = unpack_f32x2(a01);
        float2 r23 = unpack_f32x2(a23);
        float4 acc = make_float4(r01.x, r01.y, r23.x, r23.y);
        ((float4*)out)[(size_t)warp * NCH4 + c4] = acc;  // empty bins write zeros
    }
}

// ---------------------------------------------------------------------------
// Launch: inputs (metadata order) = depth, feat, ranks_depth, ranks_feat,
// ranks_bev, interval_starts, interval_lengths, [total_bev]
// interval_* are unused by the reference (segments come from sorted ranks_bev).
// ---------------------------------------------------------------------------
extern "C" void kernel_launch(void* const* d_in, const int* in_sizes, int n_in,
                              void* d_out, int out_size) {
    const float* depth       = (const float*)d_in[0];
    const float* feat        = (const float*)d_in[1];
    const void*  ranks_depth = (const void*)d_in[2];
    const void*  ranks_feat  = (const void*)d_in[3];
    const void*  ranks_bev   = (const void*)d_in[4];
    float*       out         = (float*)d_out;

    prep_kernel<<<CONV_BLOCKS + SEG_BLOCKS, 256>>>(feat, ranks_bev, ranks_depth);

    // one warp per bin, 2 warps per block: 20000 blocks of 64 threads
    bev_pool_kernel<<<(TOTAL_BEV + WPB - 1) / WPB, TPB>>>(
        depth, ranks_depth, ranks_feat, out);
}

// round 16
// speedup vs baseline: 1.0042x; 1.0042x over previous
#include <cuda_runtime.h>
#include <cuda_fp16.h>
#include <cstdint>

// Problem constants (fixed shapes per reference)
#define P_POINTS   1500000
#define TOTAL_BEV  40000
#define N_FEAT     4224        // feature rows
#define NCH        80
#define NCH4       20          // 80 channels as 20 x (4 ch)
#define BATCH      32          // points staged per warp iteration
#define WPB        8           // warps per block (256 threads) -- R13 geometry
#define BINS_PER_WARP 4        // each warp handles 4 strided bins: sums 4
                               // Poisson(37.5) bins -> relative spread halves,
                               // block-retirement waste ~18% -> ~9%, with 4x
                               // FEWER blocks (R15 showed more blocks = slower)
#define NWARPS     (TOTAL_BEV / BINS_PER_WARP)            // 10000
#define STRIDE     NWARPS                                 // bin stride per step

#define CONV_THREADS  (N_FEAT * NCH4)          // 84480: one float4 -> uint2 each
#define CONV_BLOCKS   ((CONV_THREADS + 255) / 256)        // 330
#define SEG_BLOCKS    ((TOTAL_BEV + 1 + 255) / 256)       // 157

// Scratch (no cudaMalloc allowed)
__device__ int   g_seg[TOTAL_BEV + 1];        // seg[b] = lower_bound(ranks_bev, b)
__device__ uint2 g_feat_h[N_FEAT * NCH4];     // feat fp16: row = 20 x uint2 (4 halfs), 160 B/row

// ---------------------------------------------------------------------------
// Dtype detection: index values are < 2^31, so if the buffer is really int64
// the high 32 bits of the first 4 u64 words are all zero.
// ---------------------------------------------------------------------------
__device__ __forceinline__ int detect64(const void* __restrict__ rd) {
    const unsigned long long* u = (const unsigned long long*)rd;
    unsigned long long h = (__ldg(u + 0) >> 32) | (__ldg(u + 1) >> 32) |
                           (__ldg(u + 2) >> 32) | (__ldg(u + 3) >> 32);
    return h == 0ULL;
}

__device__ __forceinline__ int ld_idx32(const void* __restrict__ p, int i, int is64) {
    if (is64) return (int)__ldg((const long long*)p + i);
    return __ldg((const int*)p + i);
}

// Packed f32x2 helpers (Blackwell f32x2 pipe; identical IEEE fma per lane)
__device__ __forceinline__ void fma_f32x2(unsigned long long& acc,
                                          unsigned long long a,
                                          unsigned long long b) {
    asm("fma.rn.f32x2 %0, %1, %2, %0;" : "+l"(acc) : "l"(a), "l"(b));
}
__device__ __forceinline__ unsigned long long pack_f32x2(float lo, float hi) {
    unsigned long long r;
    asm("mov.b64 %0, {%1, %2};" : "=l"(r) : "f"(lo), "f"(hi));
    return r;
}
__device__ __forceinline__ float2 unpack_f32x2(unsigned long long v) {
    float2 r;
    asm("mov.b64 {%0, %1}, %2;" : "=f"(r.x), "=f"(r.y) : "l"(v));
    return r;
}

// ---------------------------------------------------------------------------
// Kernel 1 (fused prep):
//   blocks [0, CONV_BLOCKS)           : feat fp32 -> fp16 (float4 -> uint2)
//   blocks [CONV_BLOCKS, +SEG_BLOCKS) : per-bin lower_bound over ranks_bev
// ---------------------------------------------------------------------------
__global__ void prep_kernel(const float* __restrict__ feat,
                            const void* __restrict__ ranks_bev,
                            const void* __restrict__ ranks_depth) {
    if (blockIdx.x < CONV_BLOCKS) {
        int i = blockIdx.x * blockDim.x + threadIdx.x;   // over N_FEAT*NCH4 float4s
        if (i < CONV_THREADS) {
            float4 v = __ldg((const float4*)feat + i);
            uint2 q;
            *(__half2*)&q.x = __float22half2_rn(make_float2(v.x, v.y));
            *(__half2*)&q.y = __float22half2_rn(make_float2(v.z, v.w));
            g_feat_h[i] = q;
        }
        return;
    }

    int b = (blockIdx.x - CONV_BLOCKS) * blockDim.x + threadIdx.x;
    if (b > TOTAL_BEV) return;
    const int is64 = detect64(ranks_depth);

    // ranks_bev is sorted-uniform: lower_bound(b) ~ b*P/B, sd <~ 620. Bracket
    // the interpolation guess (w=2048 > 3 sigma), widen on rare miss, then an
    // 11-step binary search.
    long long guess = (long long)b * P_POINTS / TOTAL_BEV;
    int lo = 0, hi = P_POINTS;
    int w = 2048;
    while (w < P_POINTS) {
        int l = (int)guess - w; if (l < 0) l = 0;
        int h = (int)guess + w; if (h > P_POINTS) h = P_POINTS;
        bool okL = (l == 0)        || (ld_idx32(ranks_bev, l - 1, is64) < b);
        bool okR = (h == P_POINTS) || (ld_idx32(ranks_bev, h,     is64) >= b);
        if (okL && okR) { lo = l; hi = h; break; }
        w <<= 2;
    }
    while (lo < hi) {
        int m = (lo + hi) >> 1;
        if (ld_idx32(ranks_bev, m, is64) < b) lo = m + 1; else hi = m;
    }
    g_seg[b] = lo;
}

// ---------------------------------------------------------------------------
// Kernel 2: 4 strided bins per warp, smem-packed staging, fp16 feat.
// Stage + consume bodies are byte-identical to R13 (FROZEN). Only the outer
// scheduling changed: warp w handles bins {w, w+10000, w+20000, w+30000}.
// ---------------------------------------------------------------------------
__global__ void __launch_bounds__(WPB * 32) bev_pool_kernel(
    const float* __restrict__ depth,       // [498432]
    const void* __restrict__ ranks_depth,  // [P]
    const void* __restrict__ ranks_feat,   // [P]
    float* __restrict__ out)               // [40000, 80]
{
    __shared__ __align__(16) unsigned long long stage[WPB][BATCH];

    const int warp = (blockIdx.x * blockDim.x + threadIdx.x) >> 5;
    const int wib  = (threadIdx.x >> 5);   // warp in block
    const int lane = threadIdx.x & 31;
    if (warp >= NWARPS) return;

    const int is64 = detect64(ranks_depth);

    const int  active = (lane < NCH4);
    const int  c4     = active ? lane : 0;   // idle lanes shadow lane 0's line
    const uint2* __restrict__ fvc = g_feat_h + c4;
    const uint4* __restrict__ stg4 = (const uint4*)&stage[wib][0];

#pragma unroll 1
    for (int k = 0; k < BINS_PER_WARP; ++k) {
        const int bin = warp + k * STRIDE;
        const int lo = g_seg[bin];
        const int hi = g_seg[bin + 1];

        unsigned long long a01 = 0ULL, a23 = 0ULL;   // f32x2 accumulators

        for (int p = lo; p < hi; p += BATCH) {
            const int n = min(BATCH, hi - p);

            // ---- stage: coalesced idx loads + depth gather, pack to smem ----
            // pack = (d_bits << 32) | (rf * NCH4): consume needs no multiply
            unsigned long long packed = 0ULL;
            if (lane < n) {
                int   rd = ld_idx32(ranks_depth, p + lane, is64);
                int   rf = ld_idx32(ranks_feat,  p + lane, is64);
                float d  = __ldg(depth + rd);
                packed = ((unsigned long long)__float_as_uint(d) << 32)
                       | (unsigned)(rf * NCH4);
            }
            stage[wib][lane] = packed;
            __syncwarp();

            // ---- consume: 2 points per LDS.128, f32x2 FMA (FROZEN) ----
            if (n == BATCH) {
                // constant trip count: ptxas fully pipelines this (do not touch)
#pragma unroll 4
                for (int j = 0; j < BATCH / 2; ++j) {
                    uint4 u = stg4[j];                 // pts 2j (x,y) and 2j+1 (z,w)
                    uint2 q0 = __ldg(fvc + u.x);
                    uint2 q1 = __ldg(fvc + u.z);
                    unsigned long long d0 = pack_f32x2(__uint_as_float(u.y), __uint_as_float(u.y));
                    unsigned long long d1 = pack_f32x2(__uint_as_float(u.w), __uint_as_float(u.w));
                    float2 p00 = __half22float2(*(const __half2*)&q0.x);
                    float2 p01 = __half22float2(*(const __half2*)&q0.y);
                    float2 p10 = __half22float2(*(const __half2*)&q1.x);
                    float2 p11 = __half22float2(*(const __half2*)&q1.y);
                    fma_f32x2(a01, pack_f32x2(p00.x, p00.y), d0);
                    fma_f32x2(a23, pack_f32x2(p01.x, p01.y), d0);
                    fma_f32x2(a01, pack_f32x2(p10.x, p10.y), d1);
                    fma_f32x2(a23, pack_f32x2(p11.x, p11.y), d1);
                }
            } else {
                // tail: pad to multiple of 8 points (= 4 pairs); padded slots
                // are (d=0, off=0) -> contribute exactly 0 (row 0 stays L1-hot)
                const int m4 = ((n + 7) & ~7) >> 1;
#pragma unroll 4
                for (int j = 0; j < m4; ++j) {
                    uint4 u = stg4[j];
                    uint2 q0 = __ldg(fvc + u.x);
                    uint2 q1 = __ldg(fvc + u.z);
                    unsigned long long d0 = pack_f32x2(__uint_as_float(u.y), __uint_as_float(u.y));
                    unsigned long long d1 = pack_f32x2(__uint_as_float(u.w), __uint_as_float(u.w));
                    float2 p00 = __half22float2(*(const __half2*)&q0.x);
                    float2 p01 = __half22float2(*(const __half2*)&q0.y);
                    float2 p10 = __half22float2(*(const __half2*)&q1.x);
                    float2 p11 = __half22float2(*(const __half2*)&q1.y);
                    fma_f32x2(a01, pack_f32x2(p00.x, p00.y), d0);
                    fma_f32x2(a23, pack_f32x2(p01.x, p01.y), d0);
                    fma_f32x2(a01, pack_f32x2(p10.x, p10.y), d1);
                    fma_f32x2(a23, pack_f32x2(p11.x, p11.y), d1);
                }
            }
            __syncwarp();   // protect stage[] before next overwrite
        }

        if (active) {
            float2 r01 = unpack_f32x2(a01);
            float2 r23 = unpack_f32x2(a23);
            float4 acc = make_float4(r01.x, r01.y, r23.x, r23.y);
            ((float4*)out)[(size_t)bin * NCH4 + c4] = acc;  // empty bins write zeros
        }
    }
}

// ---------------------------------------------------------------------------
// Launch: inputs (metadata order) = depth, feat, ranks_depth, ranks_feat,
// ranks_bev, interval_starts, interval_lengths, [total_bev]
// interval_* are unused by the reference (segments come from sorted ranks_bev).
// ---------------------------------------------------------------------------
extern "C" void kernel_launch(void* const* d_in, const int* in_sizes, int n_in,
                              void* d_out, int out_size) {
    const float* depth       = (const float*)d_in[0];
    const float* feat        = (const float*)d_in[1];
    const void*  ranks_depth = (const void*)d_in[2];
    const void*  ranks_feat  = (const void*)d_in[3];
    const void*  ranks_bev   = (const void*)d_in[4];
    float*       out         = (float*)d_out;

    prep_kernel<<<CONV_BLOCKS + SEG_BLOCKS, 256>>>(feat, ranks_bev, ranks_depth);

    // 10000 warps, 4 bins each: 1250 blocks of 256 threads
    bev_pool_kernel<<<NWARPS / WPB, WPB * 32>>>(
        depth, ranks_depth, ranks_feat, out);
}